// round 17
// baseline (speedup 1.0000x reference)
#include <cuda_runtime.h>
#include <math.h>

#define HH 128
#define WW 128
#define NN 16384          // H*W
#define BB 2
#define DD 32
#define QQ 128
#define MM 16
#define EPSF 1e-8f

// ---------------- scratch (static device allocations; no cudaMalloc) --------
__device__ float g_feat1[BB*NN*DD];
__device__ float g_k   [BB*NN*DD];   // pre-normalized k-hat
__device__ float g_q   [BB*NN*DD];   // pre-normalized q-hat
__device__ float g_w   [BB*NN*25];   // unnormalized exp(cos) weights
__device__ float g_hA  [BB*NN*QQ];
__device__ float g_hB  [BB*NN*QQ];

// ---------------- conv1: (B,H,W,3) -> relu -> (B,H,W,32) --------------------
__global__ __launch_bounds__(512) void conv1_k(const float* __restrict__ x,
                        const float* __restrict__ w,
                        const float* __restrict__ bias) {
    __shared__ float sw[3*3*3*32];
    __shared__ float sb[32];
    for (int t = threadIdx.x; t < 864; t += 512) sw[t] = w[t];
    if (threadIdx.x < 32) sb[threadIdx.x] = bias[threadIdx.x];
    __syncthreads();

    int warp = threadIdx.x >> 5;
    int co   = threadIdx.x & 31;

    #pragma unroll
    for (int ii = 0; ii < 4; ii++) {
        int gid = blockIdx.x * 64 + ii*16 + warp;    // pixel in [0, B*N)
        int b = gid >> 14, p = gid & (NN-1);
        int i = p >> 7, j = p & 127;

        float acc = sb[co];
        #pragma unroll
        for (int ky = 0; ky < 3; ky++) {
            int yi = i + ky - 1;
            if ((unsigned)yi >= HH) continue;
            #pragma unroll
            for (int kx = 0; kx < 3; kx++) {
                int xj = j + kx - 1;
                if ((unsigned)xj >= WW) continue;
                const float* xp = x + ((size_t)((b << 14) | (yi << 7) | xj)) * 3;
                const float* wp = sw + (ky*3 + kx) * 3 * 32;
                #pragma unroll
                for (int ci = 0; ci < 3; ci++) acc += xp[ci] * wp[ci*32 + co];
            }
        }
        g_feat1[(size_t)gid*32 + co] = fmaxf(acc, 0.f);
    }
}

// ------- conv2 + fused k/q projection + normalization (k-hat, q-hat) --------
__global__ __launch_bounds__(512) void conv2kq_k(const float* __restrict__ w,
                          const float* __restrict__ bias,
                          const float* __restrict__ wk,
                          const float* __restrict__ bk,
                          const float* __restrict__ wq) {
    __shared__ float sw[3*3*32*32];
    __shared__ float swk[1024], swq[1024];
    __shared__ float sb[32], sbk[32];
    for (int t = threadIdx.x; t < 9216; t += 512) sw[t] = w[t];
    for (int t = threadIdx.x; t < 1024; t += 512) { swk[t] = wk[t]; swq[t] = wq[t]; }
    if (threadIdx.x < 32) { sb[threadIdx.x] = bias[threadIdx.x]; sbk[threadIdx.x] = bk[threadIdx.x]; }
    __syncthreads();

    int warp = threadIdx.x >> 5;
    int co   = threadIdx.x & 31;

    #pragma unroll 1
    for (int ii = 0; ii < 4; ii++) {
        int gid = blockIdx.x * 64 + ii*16 + warp;
        int b = gid >> 14, p = gid & (NN-1);
        int i = p >> 7, j = p & 127;

        float acc = sb[co];
        #pragma unroll
        for (int ky = 0; ky < 3; ky++) {
            int yi = i + ky - 1;
            if ((unsigned)yi >= HH) continue;
            #pragma unroll
            for (int kx = 0; kx < 3; kx++) {
                int xj = j + kx - 1;
                if ((unsigned)xj >= WW) continue;
                const float* fin = g_feat1 + ((size_t)((b << 14) | (yi << 7) | xj)) * 32;
                const float* wp  = sw + (ky*3 + kx) * 32 * 32;
                #pragma unroll
                for (int ci = 0; ci < 32; ci++) acc += fin[ci] * wp[ci*32 + co];
            }
        }
        float fv = fmaxf(acc, 0.f);

        float ka = sbk[co], qa = 0.f;
        #pragma unroll
        for (int ci = 0; ci < 32; ci++) {
            float f = __shfl_sync(0xffffffffu, fv, ci);
            ka += f * swk[ci*32 + co];
            qa += f * swq[ci*32 + co];
        }
        float ks = ka*ka, qs = qa*qa;
        #pragma unroll
        for (int o = 16; o; o >>= 1) {
            ks += __shfl_xor_sync(0xffffffffu, ks, o);
            qs += __shfl_xor_sync(0xffffffffu, qs, o);
        }
        float kinv = rsqrtf(fmaxf(ks, 1e-30f));
        float qinv = rsqrtf(fmaxf(qs, 1e-30f));
        g_k[(size_t)gid*32 + co] = ka * kinv;
        g_q[(size_t)gid*32 + co] = qa * qinv;
    }
}

// ---------------- edge weights: exp(dot(q-hat, k-hat)), tile-based ----------
__global__ void edgew_k() {
    __shared__ float sk[32*145];
    __shared__ float sq[64*32];

    int b = blockIdx.z;
    int ti0 = blockIdx.y << 3, tj0 = blockIdx.x << 3;
    int tid = threadIdx.x;
    size_t bbase = (size_t)b << 14;

    for (int t = tid; t < 1152; t += 256) {
        int hp = t >> 3, c4 = t & 7;
        int hr = hp / 12, hc = hp - hr*12;
        int gi = min(max(ti0 + hr - 2, 0), HH-1);
        int gj = min(max(tj0 + hc - 2, 0), WW-1);
        float4 v = ((const float4*)(g_k + (bbase + (gi << 7) + gj) * 32))[c4];
        sk[(c4*4+0)*145 + hp] = v.x;
        sk[(c4*4+1)*145 + hp] = v.y;
        sk[(c4*4+2)*145 + hp] = v.z;
        sk[(c4*4+3)*145 + hp] = v.w;
    }
    for (int t = tid; t < 512; t += 256) {
        int p = t >> 3, c4 = t & 7;
        int gi = ti0 + (p >> 3), gj = tj0 + (p & 7);
        ((float4*)sq)[t] = ((const float4*)(g_q + (bbase + (gi << 7) + gj) * 32))[c4];
    }
    __syncthreads();

    int lane = tid & 31, a = tid >> 5;
    int d = min(lane, 24);
    int dr = d / 5, dc = d - dr*5;

    for (int cc = 0; cc < 8; cc++) {
        int p = a*8 + cc;
        int hidx = (a + dr)*12 + (cc + dc);
        const float* skp = sk + hidx;
        const float* sqp = sq + p*32;
        float s = 0.f;
        #pragma unroll
        for (int c = 0; c < 32; c++) s += sqp[c] * skp[c*145];
        if (lane < 25) {
            size_t gp = bbase + ((ti0 + a) << 7) + (tj0 + cc);
            g_w[gp*25 + lane] = __expf(s);
        }
    }
}

// ---------------- propagation: weighted 5x5 stencil + L2-normalize ----------
// Tile 4x8, 256 threads / 8 warps: warp = (tile column, ROW-HALF). Each warp
// computes 4 row-outputs from 8 halo rows (vs 8 outputs / 12 rows): per-warp
// critical path -33%, resident warps/SM 27.7 -> 32 (4 blocks x 8 warps,
// RF-exact). Inner (hr,a) body identical to the measured-best R16 form:
// lane = 4 adjacent channels (LDG.128 direct-global halo reads), per-warp
// (w,w)-pair weight staging (no block barriers), 2x LDS.128 + 1x LDS.64 +
// 10x fma.rn.f32x2 per (output,row).
#define PROP_W_F2 (32*32)     // 32 ops x 32 float2 (row stride 6, padded)
__global__ __launch_bounds__(256, 4) void prop_k(const float* __restrict__ hinit, int it) {
    __shared__ float2 shw[PROP_W_F2];                // 8 KB

    const float* hin = (it == 0) ? hinit : ((it & 1) ? g_hA : g_hB);
    float*       hout = (it & 1) ? g_hB : g_hA;

    int b = blockIdx.z;
    int ti0 = blockIdx.y << 3, tj0 = blockIdx.x << 2;   // 8-high, 4-wide
    int tid = threadIdx.x;
    int lane = tid & 31, w = tid >> 5;
    int c = w & 3, half = w >> 2;                    // column 0-3, row-half 0-1
    int abase = half << 2;                           // first output row (0 or 4)

    const float* hb = hin + ((size_t)b << 21);       // b*N*128
    float* hob = hout + ((size_t)b << 21);

    // per-warp weight staging: warp (c,half) stages its 4 ops; no block barrier
    const float* wb = g_w + ((size_t)b << 14) * 25;
    for (int i = lane; i < 100; i += 32) {
        int aa = i / 25, d = i - aa*25;
        int a = abase + aa;
        int r = d / 5, cl = d - r*5;
        float ww = wb[(size_t)(((ti0 + a) << 7) | (tj0 + c)) * 25 + d];
        shw[(a*4 + c)*32 + r*6 + cl] = make_float2(ww, ww);
    }
    __syncwarp();

    const unsigned long long* shw64 = (const unsigned long long*)shw;

    // hr-invariant column element-offsets for this warp's 5 taps
    unsigned cOff[5];
    #pragma unroll
    for (int dj = 0; dj < 5; dj++) {
        int gj = min(max(tj0 + c + dj - 2, 0), WW-1);
        cOff[dj] = (unsigned)gj << 7;
    }
    const float* hpl = hb + 4*lane;                  // lane's 4-channel base

    unsigned long long acc0[4], acc1[4];
    #pragma unroll
    for (int aa = 0; aa < 4; aa++) { acc0[aa] = 0ull; acc1[aa] = 0ull; }

    #pragma unroll
    for (int hrr = 0; hrr < 8; hrr++) {              // 8 halo rows for this half
        int gi = min(max(ti0 + abase + hrr - 2, 0), HH-1);
        const float* rowp = hpl + ((size_t)gi << 14);
        unsigned long long h0[5], h1[5];
        #pragma unroll
        for (int dj = 0; dj < 5; dj++) {
            ulonglong2 hv = *(const ulonglong2*)(rowp + cOff[dj]);   // LDG.128
            h0[dj] = hv.x; h1[dj] = hv.y;
        }
        #pragma unroll
        for (int aa = 0; aa < 4; aa++) {
            int r = hrr - aa;
            if (r < 0 || r > 4) continue;            // compile-time pruned
            const unsigned long long* wr = shw64 + ((abase + aa)*4 + c)*32 + r*6;
            ulonglong2 p01 = *(const ulonglong2*)(wr);   // (w0,w0),(w1,w1)
            ulonglong2 p23 = *(const ulonglong2*)(wr + 2);
            unsigned long long p4 = wr[4];
            asm("fma.rn.f32x2 %0, %1, %2, %0;" : "+l"(acc0[aa]) : "l"(h0[0]), "l"(p01.x));
            asm("fma.rn.f32x2 %0, %1, %2, %0;" : "+l"(acc1[aa]) : "l"(h1[0]), "l"(p01.x));
            asm("fma.rn.f32x2 %0, %1, %2, %0;" : "+l"(acc0[aa]) : "l"(h0[1]), "l"(p01.y));
            asm("fma.rn.f32x2 %0, %1, %2, %0;" : "+l"(acc1[aa]) : "l"(h1[1]), "l"(p01.y));
            asm("fma.rn.f32x2 %0, %1, %2, %0;" : "+l"(acc0[aa]) : "l"(h0[2]), "l"(p23.x));
            asm("fma.rn.f32x2 %0, %1, %2, %0;" : "+l"(acc1[aa]) : "l"(h1[2]), "l"(p23.x));
            asm("fma.rn.f32x2 %0, %1, %2, %0;" : "+l"(acc0[aa]) : "l"(h0[3]), "l"(p23.y));
            asm("fma.rn.f32x2 %0, %1, %2, %0;" : "+l"(acc1[aa]) : "l"(h1[3]), "l"(p23.y));
            asm("fma.rn.f32x2 %0, %1, %2, %0;" : "+l"(acc0[aa]) : "l"(h0[4]), "l"(p4));
            asm("fma.rn.f32x2 %0, %1, %2, %0;" : "+l"(acc1[aa]) : "l"(h1[4]), "l"(p4));
        }
    }

    #pragma unroll
    for (int aa = 0; aa < 4; aa++) {
        float x0, y0, z0, w0;
        asm("mov.b64 {%0,%1}, %2;" : "=f"(x0), "=f"(y0) : "l"(acc0[aa]));
        asm("mov.b64 {%0,%1}, %2;" : "=f"(z0), "=f"(w0) : "l"(acc1[aa]));
        float ss = x0*x0 + y0*y0 + z0*z0 + w0*w0;
        #pragma unroll
        for (int o = 16; o; o >>= 1) ss += __shfl_xor_sync(0xffffffffu, ss, o);
        float inv = 1.f / (sqrtf(ss) + EPSF);
        float* po = hob + ((size_t)(((ti0 + abase + aa) << 7) | (tj0 + c)) << 7);
        ((float4*)po)[lane] = make_float4(x0*inv, y0*inv, z0*inv, w0*inv);
    }
}

// ---------------- mask head: h @ w_mask, softmax over M, NCHW out -----------
__global__ void masks_k(const float* __restrict__ wm, float* __restrict__ out) {
    __shared__ float swm[QQ*MM];
    for (int t = threadIdx.x; t < QQ*MM; t += 256) swm[t] = wm[t];
    __syncthreads();

    int gid = blockIdx.x * 256 + threadIdx.x;
    int b = gid >> 14, p = gid & (NN-1);
    const float4* hr4 = (const float4*)(g_hB + (size_t)gid * QQ);  // final in hB

    float lg[MM];
    #pragma unroll
    for (int m = 0; m < MM; m++) lg[m] = 0.f;
    #pragma unroll 4
    for (int q4 = 0; q4 < 32; q4++) {
        float4 v = hr4[q4];
        const float* wrow = swm + q4*4*MM;
        #pragma unroll
        for (int m = 0; m < MM; m++) {
            lg[m] += v.x*wrow[m] + v.y*wrow[MM+m]
                   + v.z*wrow[2*MM+m] + v.w*wrow[3*MM+m];
        }
    }
    float mx = lg[0];
    #pragma unroll
    for (int m = 1; m < MM; m++) mx = fmaxf(mx, lg[m]);
    float s = 0.f;
    #pragma unroll
    for (int m = 0; m < MM; m++) { lg[m] = __expf(lg[m] - mx); s += lg[m]; }
    float r = 1.f / s;
    #pragma unroll
    for (int m = 0; m < MM; m++)
        out[(((size_t)(b*MM + m)) << 14) + p] = lg[m] * r;
}

// ---------------- launch ----------------------------------------------------
extern "C" void kernel_launch(void* const* d_in, const int* in_sizes, int n_in,
                              void* d_out, int out_size) {
    const float* x    = (const float*)d_in[0];
    // d_in[1] = edges (int32) — edge structure is analytic, unused
    const float* wc1  = (const float*)d_in[2];
    const float* bc1  = (const float*)d_in[3];
    const float* wc2  = (const float*)d_in[4];
    const float* bc2  = (const float*)d_in[5];
    const float* wk   = (const float*)d_in[6];
    const float* bk   = (const float*)d_in[7];
    const float* wq   = (const float*)d_in[8];
    const float* init = (const float*)d_in[9];
    const float* wm   = (const float*)d_in[10];
    float* out = (float*)d_out;

    conv1_k  <<<BB*NN/64, 512>>>(x, wc1, bc1);
    conv2kq_k<<<BB*NN/64, 512>>>(wc2, bc2, wk, bk, wq);
    edgew_k  <<<dim3(WW/8, HH/8, BB), 256>>>();

    for (int it = 0; it < 32; it++) {
        prop_k<<<dim3(WW/4, HH/8, BB), 256>>>(init, it);
    }
    masks_k<<<BB*NN/256, 256>>>(wm, out);
}